// round 13
// baseline (speedup 1.0000x reference)
#include <cuda_runtime.h>

// CrossAttention_5385888989393 — reduced channel-attention, TF32 tensor cores.
// R13: middle (dots+softmax+U) fully fused, row-split 4x -> 256 CTAs, all in
// smem, no dots round-trip. Numerics bit-identical (rel_err 6.493987e-4).

#define BATCH 8
#define NHEADS 8
#define DH 64
#define CDIM 512
#define NSP 4096

__device__ float g_G[BATCH * CDIM * CDIM];
__device__ float g_T[BATCH * NHEADS * CDIM * DH];
__device__ float g_U[BATCH * CDIM * CDIM];
__device__ float g_M[BATCH * CDIM * CDIM];
__device__ float g_cn[BATCH * CDIM * NSP];     // tf32(f_n)
__device__ float g_cWk[CDIM * CDIM];           // tf32(Wkv k-half)
__device__ float g_cWout[CDIM * CDIM];         // tf32(Wout)

__device__ __forceinline__ unsigned f2tf(float f) {
    unsigned u;
    asm("cvt.rna.tf32.f32 %0, %1;" : "=r"(u) : "f"(f));
    return u;
}

__device__ __forceinline__ void cp16(void* sdst, const void* gsrc) {
    unsigned s = (unsigned)__cvta_generic_to_shared(sdst);
    asm volatile("cp.async.cg.shared.global [%0], [%1], 16;\n" :: "r"(s), "l"(gsrc));
}
__device__ __forceinline__ void cp_commit() {
    asm volatile("cp.async.commit_group;\n");
}

// ---------------------------------------------------------------------------
// Fused tf32 conversion (f_n, Wkv k-half, Wout) in one launch.
// ---------------------------------------------------------------------------
__global__ void cvt_all_k(const float4* __restrict__ fn, uint4* __restrict__ cn,
                          const float4* __restrict__ wkv, uint4* __restrict__ cwk,
                          const float4* __restrict__ wout, uint4* __restrict__ cwout)
{
    const int NB = BATCH * CDIM * NSP / 4;   // 4194304
    const int NW = CDIM * CDIM / 4;          // 65536
    int i = blockIdx.x * blockDim.x + threadIdx.x;
    const float4* src; uint4* dst; int off;
    if (i < NB)          { src = fn;   dst = cn;    off = i; }
    else if (i < NB + NW){ src = wkv;  dst = cwk;   off = i - NB; }
    else                 { src = wout; dst = cwout; off = i - NB - NW; }
    float4 v = src[off];
    uint4 o;
    o.x = f2tf(v.x); o.y = f2tf(v.y); o.z = f2tf(v.z); o.w = f2tf(v.w);
    dst[off] = o;
}

// ---------------------------------------------------------------------------
// cp.async-fed TF32 GEMM. CVTA=true: A raw fp32 via LDG+f2tf+STS (prefetched);
// B via cp.async from pre-rounded gmem.
// ---------------------------------------------------------------------------
template <int BM, int BN, int WRR, int WCC, bool TRB, bool BIAS, bool CVTOUT, bool CVTA>
__global__ void __launch_bounds__(256)
tf32gemm_ca(const float* __restrict__ A0, const float* __restrict__ B0,
            float* __restrict__ C0, const float* __restrict__ bias,
            int M, int N, int K,
            long long sA1, long long sA2, long long sB1, long long sB2,
            long long sC1, long long sC2, int B2, float alpha)
{
    constexpr int BK = 32;
    constexpr int WM = BM / WRR;
    constexpr int WN = BN / WCC;
    constexpr int IT = WM / 16;
    constexpr int JT = WN / 8;
    static_assert(WRR * WCC == 8, "8 warps");

    constexpr int AW  = BK + 4;
    constexpr int BSR = TRB ? BN : BK;
    constexpr int BSC = TRB ? (BK + 4) : (BN + 8);
    constexpr int A_WORDS = BM * AW;
    constexpr int B_WORDS = BSR * BSC;

    constexpr int A_T4   = (BM * (BK / 4)) / 256;
    constexpr int BT_T4  = (BN * (BK / 4)) / 256;
    constexpr int BNN_T4 = (BK * (BN / 4)) / 256;
    constexpr int B_T4   = TRB ? BT_T4 : BNN_T4;

    extern __shared__ unsigned sm[];
    unsigned* Asm = sm;
    unsigned* Bsm = sm + 2 * A_WORDS;

    int z = blockIdx.z;
    int i1 = z / B2, i2 = z - i1 * B2;
    const float* A  = A0 + (size_t)i1 * sA1 + (size_t)i2 * sA2;
    const float* Bp = B0 + (size_t)i1 * sB1 + (size_t)i2 * sB2;
    float*       Cp = C0 + (size_t)i1 * sC1 + (size_t)i2 * sC2;

    const int tid  = threadIdx.x;
    const int lane = tid & 31;
    const int wid  = tid >> 5;
    const int wr   = wid / WCC;
    const int wc   = wid % WCC;
    const int g    = lane >> 2;
    const int tq   = lane & 3;

    const int rowBase = blockIdx.y * BM;
    const int colBase = blockIdx.x * BN;

    float c[IT][JT][4];
    #pragma unroll
    for (int i = 0; i < IT; i++)
        #pragma unroll
        for (int j = 0; j < JT; j++)
            c[i][j][0] = c[i][j][1] = c[i][j][2] = c[i][j][3] = 0.f;

    float4 pa[CVTA ? A_T4 : 1];

    auto load_A_async = [&](int s, int k0) {
        #pragma unroll
        for (int it = 0; it < A_T4; it++) {
            int t = tid + it * 256;
            int r = t >> 3, c4 = (t & 7) << 2;
            cp16(&Asm[s * A_WORDS + r * AW + c4],
                 A + (size_t)(rowBase + r) * K + k0 + c4);
        }
    };
    auto load_A_regs = [&](int k0) {
        #pragma unroll
        for (int it = 0; it < A_T4; it++) {
            int t = tid + it * 256;
            int r = t >> 3, c4 = (t & 7) << 2;
            pa[it] = *reinterpret_cast<const float4*>(
                A + (size_t)(rowBase + r) * K + k0 + c4);
        }
    };
    auto sts_A = [&](int s) {
        #pragma unroll
        for (int it = 0; it < A_T4; it++) {
            int t = tid + it * 256;
            int r = t >> 3, c4 = (t & 7) << 2;
            unsigned* dst = &Asm[s * A_WORDS + r * AW + c4];
            dst[0] = f2tf(pa[it].x); dst[1] = f2tf(pa[it].y);
            dst[2] = f2tf(pa[it].z); dst[3] = f2tf(pa[it].w);
        }
    };
    auto load_B = [&](int s, int k0) {
        if (TRB) {
            #pragma unroll
            for (int it = 0; it < B_T4; it++) {
                int t = tid + it * 256;
                int r = t >> 3, c4 = (t & 7) << 2;
                cp16(&Bsm[s * B_WORDS + r * BSC + c4],
                     Bp + (size_t)(colBase + r) * K + k0 + c4);
            }
        } else {
            #pragma unroll
            for (int it = 0; it < B_T4; it++) {
                int t = tid + it * 256;
                int r = t / (BN / 4), c4 = (t % (BN / 4)) << 2;
                cp16(&Bsm[s * B_WORDS + r * BSC + c4],
                     Bp + (size_t)(k0 + r) * N + colBase + c4);
            }
        }
    };

    if (CVTA) {
        load_A_regs(0);
        load_B(0, 0);
        cp_commit();
        sts_A(0);
        asm volatile("cp.async.wait_group 0;\n");
        __syncthreads();
    } else {
        load_A_async(0, 0);
        load_B(0, 0);
        cp_commit();
    }

    int buf = 0;
    for (int k0 = 0; k0 < K; k0 += BK) {
        const bool has_next = (k0 + BK) < K;
        if (has_next) {
            if (CVTA) {
                load_A_regs(k0 + BK);
                load_B(buf ^ 1, k0 + BK);
                cp_commit();
            } else {
                load_A_async(buf ^ 1, k0 + BK);
                load_B(buf ^ 1, k0 + BK);
                cp_commit();
            }
        }

        if (!CVTA) {
            if (has_next) { asm volatile("cp.async.wait_group 1;\n"); }
            else          { asm volatile("cp.async.wait_group 0;\n"); }
            __syncthreads();
        }

        const unsigned* Ab = Asm + buf * A_WORDS;
        const unsigned* Bb = Bsm + buf * B_WORDS;

        #pragma unroll
        for (int ks = 0; ks < BK; ks += 8) {
            unsigned a[IT][4], b[JT][2];
            #pragma unroll
            for (int i = 0; i < IT; i++) {
                int m = wr * WM + i * 16;
                a[i][0] = Ab[(m + g) * AW + ks + tq];
                a[i][1] = Ab[(m + g + 8) * AW + ks + tq];
                a[i][2] = Ab[(m + g) * AW + ks + tq + 4];
                a[i][3] = Ab[(m + g + 8) * AW + ks + tq + 4];
            }
            #pragma unroll
            for (int j = 0; j < JT; j++) {
                int n = wc * WN + j * 8;
                if (TRB) {
                    b[j][0] = Bb[(n + g) * BSC + ks + tq];
                    b[j][1] = Bb[(n + g) * BSC + ks + tq + 4];
                } else {
                    b[j][0] = Bb[(ks + tq) * BSC + n + g];
                    b[j][1] = Bb[(ks + tq + 4) * BSC + n + g];
                }
            }
            #pragma unroll
            for (int i = 0; i < IT; i++)
                #pragma unroll
                for (int j = 0; j < JT; j++)
                    asm volatile(
                        "mma.sync.aligned.m16n8k8.row.col.f32.tf32.tf32.f32 "
                        "{%0,%1,%2,%3}, {%4,%5,%6,%7}, {%8,%9}, {%0,%1,%2,%3};\n"
                        : "+f"(c[i][j][0]), "+f"(c[i][j][1]),
                          "+f"(c[i][j][2]), "+f"(c[i][j][3])
                        : "r"(a[i][0]), "r"(a[i][1]), "r"(a[i][2]), "r"(a[i][3]),
                          "r"(b[j][0]), "r"(b[j][1]));
        }

        if (CVTA) {
            __syncthreads();
            if (has_next) {
                sts_A(buf ^ 1);
                asm volatile("cp.async.wait_group 0;\n");
                __syncthreads();
            }
        } else {
            __syncthreads();
        }
        buf ^= 1;
    }

    #pragma unroll
    for (int i = 0; i < IT; i++) {
        int row = rowBase + wr * WM + i * 16 + g;
        float bv0 = BIAS ? bias[row] : 0.f;
        float bv1 = BIAS ? bias[row + 8] : 0.f;
        #pragma unroll
        for (int j = 0; j < JT; j++) {
            int col = colBase + wc * WN + j * 8 + 2 * tq;
            float v00 = alpha * c[i][j][0] + bv0;
            float v01 = alpha * c[i][j][1] + bv0;
            float v10 = alpha * c[i][j][2] + bv1;
            float v11 = alpha * c[i][j][3] + bv1;
            if (CVTOUT) {
                v00 = __uint_as_float(f2tf(v00));
                v01 = __uint_as_float(f2tf(v01));
                v10 = __uint_as_float(f2tf(v10));
                v11 = __uint_as_float(f2tf(v11));
            }
            Cp[(size_t)row * N + col]           = v00;
            Cp[(size_t)row * N + col + 1]       = v01;
            Cp[(size_t)(row + 8) * N + col]     = v10;
            Cp[(size_t)(row + 8) * N + col + 1] = v11;
        }
    }
}

// ---------------------------------------------------------------------------
// Fully fused middle, row-split: CTA (r0, z) computes 16 rows of
//   dots = (Wq_h @ T_bh)*scale -> softmax -> U = attn @ Wv_h (tf32 out).
// grid (4, 64); 256 threads; thread (tm=tid>>4 row, tn=tid&15 col-group).
// Per-element accumulation strictly ascending k; softmax op-sequence identical
// to prior rounds -> bit-identical output.
// ---------------------------------------------------------------------------
__global__ void __launch_bounds__(256)
attn_fused(const float* __restrict__ Wq, const float* __restrict__ T,
           const float* __restrict__ WkvV, float* __restrict__ U)
{
    const int z  = blockIdx.y;              // b*NHEADS + h
    const int b  = z / NHEADS, h = z % NHEADS;
    const int r0 = blockIdx.x * 16;         // row block within the head
    const float* Aq = Wq   + (size_t)h * DH * CDIM + (size_t)r0 * CDIM;  // 16x512
    const float* Tb = T    + (size_t)z * CDIM * DH;                      // 512x64
    const float* Wv = WkvV + (size_t)h * DH * CDIM;                      // 64x512
    float* Ub = U + (size_t)b * CDIM * CDIM + (size_t)(h * DH + r0) * CDIM;

    __shared__ float sQ[16 * 68];     // Wq slab  (16x64)
    __shared__ float sT[64 * 68];     // T slab / Wv slab (64x64)
    __shared__ float sAt[16 * 68];    // dots -> attn (16x64)

    const int tid  = threadIdx.x;
    const int tm   = tid >> 4;        // 0..15 (row)
    const int tn   = tid & 15;        // 0..15 (col group of 4)
    const int lane = tid & 31;
    const int wrp  = tid >> 5;

    // ---- Phase 1: dots rows = Wq rows @ T, K=512 ascending (slabs of 64)
    float acc[4] = {};
    for (int k0 = 0; k0 < CDIM; k0 += 64) {
        {   // Wq slab: 16x64 = 256 float4, one per thread
            int r = tid >> 4, c4 = (tid & 15) << 2;
            float4 v = *(const float4*)(Aq + (size_t)r * CDIM + k0 + c4);
            sQ[r * 68 + c4 + 0] = v.x; sQ[r * 68 + c4 + 1] = v.y;
            sQ[r * 68 + c4 + 2] = v.z; sQ[r * 68 + c4 + 3] = v.w;
        }
        #pragma unroll
        for (int it = 0; it < 4; it++) {   // T slab: 64x64 = 1024 float4
            int t = tid + it * 256;
            int r = t >> 4, c4 = (t & 15) << 2;
            float4 v = *(const float4*)(Tb + (size_t)(k0 + r) * DH + c4);
            sT[r * 68 + c4 + 0] = v.x; sT[r * 68 + c4 + 1] = v.y;
            sT[r * 68 + c4 + 2] = v.z; sT[r * 68 + c4 + 3] = v.w;
        }
        __syncthreads();
        for (int kk = 0; kk < 64; kk++) {
            float ra = sQ[tm * 68 + kk];
            float4 rb = *(const float4*)&sT[kk * 68 + tn * 4];
            acc[0] = fmaf(ra, rb.x, acc[0]);
            acc[1] = fmaf(ra, rb.y, acc[1]);
            acc[2] = fmaf(ra, rb.z, acc[2]);
            acc[3] = fmaf(ra, rb.w, acc[3]);
        }
        __syncthreads();
    }
    #pragma unroll
    for (int j = 0; j < 4; j++)
        sAt[tm * 68 + tn * 4 + j] = 0.125f * acc[j];
    __syncthreads();

    // ---- Phase 2: softmax on 16 rows (2 rows per warp, identical op seq)
    for (int row = wrp; row < 16; row += 8) {
        float* r = sAt + row * 68;
        float a = r[lane];
        float bb = r[lane + 32];
        float m = fmaxf(a, bb);
        #pragma unroll
        for (int o = 16; o > 0; o >>= 1) m = fmaxf(m, __shfl_xor_sync(0xffffffffu, m, o));
        float e1 = __expf(a - m);
        float e2 = __expf(bb - m);
        float ss = e1 + e2;
        #pragma unroll
        for (int o = 16; o > 0; o >>= 1) ss += __shfl_xor_sync(0xffffffffu, ss, o);
        float inv = 1.0f / ss;
        r[lane]      = e1 * inv;
        r[lane + 32] = e2 * inv;
    }
    __syncthreads();

    // ---- Phase 3: U rows = attn rows @ Wv, K=64 ascending, n-slabs of 64
    for (int n0 = 0; n0 < CDIM; n0 += 64) {
        #pragma unroll
        for (int it = 0; it < 4; it++) {   // Wv slab: 64x64 (rows=k, cols=n)
            int t = tid + it * 256;
            int r = t >> 4, c4 = (t & 15) << 2;
            float4 v = *(const float4*)(Wv + (size_t)r * CDIM + n0 + c4);
            sT[r * 68 + c4 + 0] = v.x; sT[r * 68 + c4 + 1] = v.y;
            sT[r * 68 + c4 + 2] = v.z; sT[r * 68 + c4 + 3] = v.w;
        }
        __syncthreads();
        float u[4] = {};
        for (int k = 0; k < 64; k++) {
            float ra = sAt[tm * 68 + k];
            float4 rb = *(const float4*)&sT[k * 68 + tn * 4];
            u[0] = fmaf(ra, rb.x, u[0]);
            u[1] = fmaf(ra, rb.y, u[1]);
            u[2] = fmaf(ra, rb.z, u[2]);
            u[3] = fmaf(ra, rb.w, u[3]);
        }
        uint4 o;
        o.x = f2tf(u[0]); o.y = f2tf(u[1]); o.z = f2tf(u[2]); o.w = f2tf(u[3]);
        *reinterpret_cast<uint4*>(Ub + (size_t)tm * CDIM + n0 + tn * 4) = o;
        __syncthreads();
    }
}

extern "C" void kernel_launch(void* const* d_in, const int* in_sizes, int n_in,
                              void* d_out, int out_size)
{
    const float* f_m  = (const float*)d_in[0];
    const float* f_n  = (const float*)d_in[1];
    const float* Wq   = (const float*)d_in[2];
    const float* Wkv  = (const float*)d_in[3];
    const float* Wout = (const float*)d_in[4];
    const float* bout = (const float*)d_in[5];
    float* out = (float*)d_out;

    float *G, *T, *U, *Mm, *cn, *cWk, *cWout;
    cudaGetSymbolAddress((void**)&G,     g_G);
    cudaGetSymbolAddress((void**)&T,     g_T);
    cudaGetSymbolAddress((void**)&U,     g_U);
    cudaGetSymbolAddress((void**)&Mm,    g_M);
    cudaGetSymbolAddress((void**)&cn,    g_cn);
    cudaGetSymbolAddress((void**)&cWk,   g_cWk);
    cudaGetSymbolAddress((void**)&cWout, g_cWout);

    const long long CF  = (long long)CDIM * NSP;
    const long long CC  = (long long)CDIM * CDIM;
    const long long THD = (long long)CDIM * DH;

    constexpr int SM_128_NT = (2 * 128 * 36 + 2 * 128 * 36) * 4;   // 73728
    constexpr int SM_64_NT  = (2 * 64 * 36 + 2 * 64 * 36) * 4;     // 36864
    constexpr int SM_128_NN = (2 * 128 * 36 + 2 * 32 * 136) * 4;   // 71680
    constexpr int SM_256_NN = (2 * 256 * 36 + 2 * 32 * 136) * 4;   // 108544

    cudaFuncSetAttribute(tf32gemm_ca<128, 128, 2, 4, true, false, true, true>,
                         cudaFuncAttributeMaxDynamicSharedMemorySize, SM_128_NT);
    cudaFuncSetAttribute(tf32gemm_ca<64, 64, 2, 4, true, false, false, false>,
                         cudaFuncAttributeMaxDynamicSharedMemorySize, SM_64_NT);
    cudaFuncSetAttribute(tf32gemm_ca<128, 128, 2, 4, false, false, true, false>,
                         cudaFuncAttributeMaxDynamicSharedMemorySize, SM_128_NN);
    cudaFuncSetAttribute(tf32gemm_ca<256, 128, 4, 2, false, true, false, false>,
                         cudaFuncAttributeMaxDynamicSharedMemorySize, SM_256_NN);

    // 0) tf32 pre-conversions (f_n, Wkv k-half, Wout) in ONE launch
    {
        const int NB = BATCH * CDIM * NSP / 4;     // 4194304
        const int NW = CDIM * CDIM / 4;            // 65536
        int total = NB + 2 * NW;                   // 4325376 = 16896*256
        cvt_all_k<<<total / 256, 256>>>(
            (const float4*)f_n, (uint4*)cn,
            (const float4*)Wkv, (uint4*)cWk, (const float4*)Wout, (uint4*)cWout);
    }

    // 1) G[b] = tf32(f_m[b]) @ cn[b]^T  (NT, K=4096), A cvt in-loop, out tf32
    tf32gemm_ca<128, 128, 2, 4, true, false, true, true>
        <<<dim3(4, 4, BATCH), 256, SM_128_NT>>>(
        f_m, cn, G, nullptr, CDIM, CDIM, NSP,
        CF, 0, CF, 0, CC, 0, 1, 1.0f);

    // 2) T[b,h] = G[b] @ cWk_h^T  (NT, K=512), out fp32
    tf32gemm_ca<64, 64, 2, 4, true, false, false, false>
        <<<dim3(1, 8, BATCH * NHEADS), 256, SM_64_NT>>>(
        G, cWk, T, nullptr, CDIM, DH, CDIM,
        CC, 0, 0, (long long)DH * CDIM, (long long)NHEADS * THD, THD,
        NHEADS, 1.0f);

    // 3-5) fused dots + softmax + U, row-split 4x  (256 CTAs)
    attn_fused<<<dim3(4, BATCH * NHEADS), 256>>>(
        Wq, T, Wkv + (size_t)CDIM * CDIM, U);

    // 6) M[b] = cWout @ U[b]   (NN, K=512), out tf32-rounded
    tf32gemm_ca<128, 128, 2, 4, false, false, true, false>
        <<<dim3(4, 4, BATCH), 256, SM_128_NN>>>(
        cWout, U, Mm, nullptr, CDIM, CDIM, CDIM,
        0, 0, CC, 0, CC, 0, 1, 1.0f);

    // 7) out[b] = M[b] @ cn[b] + bout  (NN, K=512, bias), 256x128 tiles
    tf32gemm_ca<256, 128, 4, 2, false, true, false, false>
        <<<dim3(32, 2, BATCH), 256, SM_256_NN>>>(
        Mm, cn, out, bout, CDIM, NSP, CDIM,
        CC, 0, CF, 0, CF, 0, 1, 1.0f);
}

// round 14
// speedup vs baseline: 1.0344x; 1.0344x over previous
#include <cuda_runtime.h>

// CrossAttention_5385888989393 — reduced channel-attention, TF32 tensor cores.
// R14: best-measured components. cvt 4-way fused; GEMM1 pure cp.async (CVTA
// reverted); middle = dots(128 CTAs, softmax fused in epilogue) + U sgemm;
// GEMM7 256x128. Numerics bit-identical (rel_err 6.493987e-4).

#define BATCH 8
#define NHEADS 8
#define DH 64
#define CDIM 512
#define NSP 4096

__device__ float g_G[BATCH * CDIM * CDIM];
__device__ float g_T[BATCH * NHEADS * CDIM * DH];
__device__ float g_dots[BATCH * NHEADS * DH * DH];
__device__ float g_U[BATCH * CDIM * CDIM];
__device__ float g_M[BATCH * CDIM * CDIM];
__device__ float g_cm[BATCH * CDIM * NSP];     // tf32(f_m)
__device__ float g_cn[BATCH * CDIM * NSP];     // tf32(f_n)
__device__ float g_cWk[CDIM * CDIM];           // tf32(Wkv k-half)
__device__ float g_cWout[CDIM * CDIM];         // tf32(Wout)

__device__ __forceinline__ unsigned f2tf(float f) {
    unsigned u;
    asm("cvt.rna.tf32.f32 %0, %1;" : "=r"(u) : "f"(f));
    return u;
}

__device__ __forceinline__ void cp16(void* sdst, const void* gsrc) {
    unsigned s = (unsigned)__cvta_generic_to_shared(sdst);
    asm volatile("cp.async.cg.shared.global [%0], [%1], 16;\n" :: "r"(s), "l"(gsrc));
}
__device__ __forceinline__ void cp_commit() {
    asm volatile("cp.async.commit_group;\n");
}

// ---------------------------------------------------------------------------
// Fused tf32 conversion of all four operands in one launch.
// ---------------------------------------------------------------------------
__global__ void cvt_all_k(const float4* __restrict__ fm, uint4* __restrict__ cm,
                          const float4* __restrict__ fn, uint4* __restrict__ cn,
                          const float4* __restrict__ wkv, uint4* __restrict__ cwk,
                          const float4* __restrict__ wout, uint4* __restrict__ cwout)
{
    const int NB = BATCH * CDIM * NSP / 4;   // 4194304
    const int NW = CDIM * CDIM / 4;          // 65536
    int i = blockIdx.x * blockDim.x + threadIdx.x;
    const float4* src; uint4* dst; int off;
    if (i < NB)               { src = fm;   dst = cm;    off = i; }
    else if (i < 2 * NB)      { src = fn;   dst = cn;    off = i - NB; }
    else if (i < 2 * NB + NW) { src = wkv;  dst = cwk;   off = i - 2 * NB; }
    else                      { src = wout; dst = cwout; off = i - 2 * NB - NW; }
    float4 v = src[off];
    uint4 o;
    o.x = f2tf(v.x); o.y = f2tf(v.y); o.z = f2tf(v.z); o.w = f2tf(v.w);
    dst[off] = o;
}

// ---------------------------------------------------------------------------
// cp.async-fed TF32 GEMM (operands pre-rounded tf32 in gmem).
//   BK=32, 2-stage smem double buffer, 256 threads = 8 warps (WRR x WCC).
// ---------------------------------------------------------------------------
template <int BM, int BN, int WRR, int WCC, bool TRB, bool BIAS, bool CVTOUT>
__global__ void __launch_bounds__(256)
tf32gemm_ca(const float* __restrict__ A0, const float* __restrict__ B0,
            float* __restrict__ C0, const float* __restrict__ bias,
            int M, int N, int K,
            long long sA1, long long sA2, long long sB1, long long sB2,
            long long sC1, long long sC2, int B2, float alpha)
{
    constexpr int BK = 32;
    constexpr int WM = BM / WRR;
    constexpr int WN = BN / WCC;
    constexpr int IT = WM / 16;
    constexpr int JT = WN / 8;
    static_assert(WRR * WCC == 8, "8 warps");

    constexpr int AW  = BK + 4;
    constexpr int BSR = TRB ? BN : BK;
    constexpr int BSC = TRB ? (BK + 4) : (BN + 8);
    constexpr int A_WORDS = BM * AW;
    constexpr int B_WORDS = BSR * BSC;

    constexpr int A_T4   = (BM * (BK / 4)) / 256;
    constexpr int BT_T4  = (BN * (BK / 4)) / 256;
    constexpr int BNN_T4 = (BK * (BN / 4)) / 256;
    constexpr int B_T4   = TRB ? BT_T4 : BNN_T4;

    extern __shared__ unsigned sm[];
    unsigned* Asm = sm;
    unsigned* Bsm = sm + 2 * A_WORDS;

    int z = blockIdx.z;
    int i1 = z / B2, i2 = z - i1 * B2;
    const float* A  = A0 + (size_t)i1 * sA1 + (size_t)i2 * sA2;
    const float* Bp = B0 + (size_t)i1 * sB1 + (size_t)i2 * sB2;
    float*       Cp = C0 + (size_t)i1 * sC1 + (size_t)i2 * sC2;

    const int tid  = threadIdx.x;
    const int lane = tid & 31;
    const int wid  = tid >> 5;
    const int wr   = wid / WCC;
    const int wc   = wid % WCC;
    const int g    = lane >> 2;
    const int tq   = lane & 3;

    const int rowBase = blockIdx.y * BM;
    const int colBase = blockIdx.x * BN;

    float c[IT][JT][4];
    #pragma unroll
    for (int i = 0; i < IT; i++)
        #pragma unroll
        for (int j = 0; j < JT; j++)
            c[i][j][0] = c[i][j][1] = c[i][j][2] = c[i][j][3] = 0.f;

    auto load_tile = [&](int s, int k0) {
        #pragma unroll
        for (int it = 0; it < A_T4; it++) {
            int t = tid + it * 256;
            int r = t >> 3, c4 = (t & 7) << 2;
            cp16(&Asm[s * A_WORDS + r * AW + c4],
                 A + (size_t)(rowBase + r) * K + k0 + c4);
        }
        if (TRB) {
            #pragma unroll
            for (int it = 0; it < B_T4; it++) {
                int t = tid + it * 256;
                int r = t >> 3, c4 = (t & 7) << 2;
                cp16(&Bsm[s * B_WORDS + r * BSC + c4],
                     Bp + (size_t)(colBase + r) * K + k0 + c4);
            }
        } else {
            #pragma unroll
            for (int it = 0; it < B_T4; it++) {
                int t = tid + it * 256;
                int r = t / (BN / 4), c4 = (t % (BN / 4)) << 2;
                cp16(&Bsm[s * B_WORDS + r * BSC + c4],
                     Bp + (size_t)(k0 + r) * N + colBase + c4);
            }
        }
        cp_commit();
    };

    load_tile(0, 0);

    int buf = 0;
    for (int k0 = 0; k0 < K; k0 += BK) {
        const bool has_next = (k0 + BK) < K;
        if (has_next) load_tile(buf ^ 1, k0 + BK);

        if (has_next) { asm volatile("cp.async.wait_group 1;\n"); }
        else          { asm volatile("cp.async.wait_group 0;\n"); }
        __syncthreads();

        const unsigned* Ab = Asm + buf * A_WORDS;
        const unsigned* Bb = Bsm + buf * B_WORDS;

        #pragma unroll
        for (int ks = 0; ks < BK; ks += 8) {
            unsigned a[IT][4], b[JT][2];
            #pragma unroll
            for (int i = 0; i < IT; i++) {
                int m = wr * WM + i * 16;
                a[i][0] = Ab[(m + g) * AW + ks + tq];
                a[i][1] = Ab[(m + g + 8) * AW + ks + tq];
                a[i][2] = Ab[(m + g) * AW + ks + tq + 4];
                a[i][3] = Ab[(m + g + 8) * AW + ks + tq + 4];
            }
            #pragma unroll
            for (int j = 0; j < JT; j++) {
                int n = wc * WN + j * 8;
                if (TRB) {
                    b[j][0] = Bb[(n + g) * BSC + ks + tq];
                    b[j][1] = Bb[(n + g) * BSC + ks + tq + 4];
                } else {
                    b[j][0] = Bb[(ks + tq) * BSC + n + g];
                    b[j][1] = Bb[(ks + tq + 4) * BSC + n + g];
                }
            }
            #pragma unroll
            for (int i = 0; i < IT; i++)
                #pragma unroll
                for (int j = 0; j < JT; j++)
                    asm volatile(
                        "mma.sync.aligned.m16n8k8.row.col.f32.tf32.tf32.f32 "
                        "{%0,%1,%2,%3}, {%4,%5,%6,%7}, {%8,%9}, {%0,%1,%2,%3};\n"
                        : "+f"(c[i][j][0]), "+f"(c[i][j][1]),
                          "+f"(c[i][j][2]), "+f"(c[i][j][3])
                        : "r"(a[i][0]), "r"(a[i][1]), "r"(a[i][2]), "r"(a[i][3]),
                          "r"(b[j][0]), "r"(b[j][1]));
        }
        __syncthreads();
        buf ^= 1;
    }

    #pragma unroll
    for (int i = 0; i < IT; i++) {
        int row = rowBase + wr * WM + i * 16 + g;
        float bv0 = BIAS ? bias[row] : 0.f;
        float bv1 = BIAS ? bias[row + 8] : 0.f;
        #pragma unroll
        for (int j = 0; j < JT; j++) {
            int col = colBase + wc * WN + j * 8 + 2 * tq;
            float v00 = alpha * c[i][j][0] + bv0;
            float v01 = alpha * c[i][j][1] + bv0;
            float v10 = alpha * c[i][j][2] + bv1;
            float v11 = alpha * c[i][j][3] + bv1;
            if (CVTOUT) {
                v00 = __uint_as_float(f2tf(v00));
                v01 = __uint_as_float(f2tf(v01));
                v10 = __uint_as_float(f2tf(v10));
                v11 = __uint_as_float(f2tf(v11));
            }
            Cp[(size_t)row * N + col]           = v00;
            Cp[(size_t)row * N + col + 1]       = v01;
            Cp[(size_t)(row + 8) * N + col]     = v10;
            Cp[(size_t)(row + 8) * N + col + 1] = v11;
        }
    }
}

// ---------------------------------------------------------------------------
// dots + softmax fused: one CTA computes a 32-row block of
//   dots = (Wq_h @ T_bh)*0.125  then softmax rows -> attn to gmem.
// grid (2, 64). Per-element K ascending; epilogue = 0.125*acc + 0.0f staged
// to smem; softmax op-sequence identical to softmax64 -> bit-identical.
// ---------------------------------------------------------------------------
__global__ void __launch_bounds__(256)
dots_sm(const float* __restrict__ Wq, const float* __restrict__ T,
        float* __restrict__ dots)
{
    const int z  = blockIdx.y;              // b*NHEADS + h
    const int h  = z % NHEADS;
    const int r0 = blockIdx.x * 32;
    const float* Aq = Wq + (size_t)h * DH * CDIM + (size_t)r0 * CDIM;  // 32x512
    const float* Tb = T  + (size_t)z * CDIM * DH;                      // 512x64
    float* Db = dots + (size_t)z * DH * DH + (size_t)r0 * 64;

    __shared__ float As[32][36];   // [k][m]
    __shared__ float Bs[32][68];   // [k][n]
    __shared__ float sD[32 * 64];  // staged dots

    const int tid  = threadIdx.x;
    const int tn   = tid & 15;     // col group (4 cols)
    const int tm   = tid >> 4;     // row group (2 rows)
    const int lane = tid & 31;
    const int wrp  = tid >> 5;

    float acc[2][4] = {};

    for (int k0 = 0; k0 < CDIM; k0 += 32) {
        {   // A tile 32x32 (K-contig), store transposed As[k][m]
            int r = tid >> 3, c4 = (tid & 7) << 2;
            float4 v = *(const float4*)(Aq + (size_t)r * CDIM + k0 + c4);
            As[c4 + 0][r] = v.x; As[c4 + 1][r] = v.y;
            As[c4 + 2][r] = v.z; As[c4 + 3][r] = v.w;
        }
        #pragma unroll
        for (int it = 0; it < 2; it++) {   // B tile 32k x 64n
            int t = tid + it * 256;
            int r = t >> 4, c4 = (t & 15) << 2;
            float4 v = *(const float4*)(Tb + (size_t)(k0 + r) * DH + c4);
            *reinterpret_cast<float4*>(&Bs[r][c4]) = v;
        }
        __syncthreads();

        #pragma unroll
        for (int k = 0; k < 32; k++) {
            float ra[2], rb[4];
            #pragma unroll
            for (int i = 0; i < 2; i++) ra[i] = As[k][tm * 2 + i];
            #pragma unroll
            for (int j = 0; j < 4; j++) rb[j] = Bs[k][tn * 4 + j];
            #pragma unroll
            for (int i = 0; i < 2; i++)
                #pragma unroll
                for (int j = 0; j < 4; j++)
                    acc[i][j] = fmaf(ra[i], rb[j], acc[i][j]);
        }
        __syncthreads();
    }

    // stage (identical to old epilogue: alpha*acc + 0.0f)
    #pragma unroll
    for (int i = 0; i < 2; i++)
        #pragma unroll
        for (int j = 0; j < 4; j++)
            sD[(tm * 2 + i) * 64 + tn * 4 + j] = 0.125f * acc[i][j] + 0.0f;
    __syncthreads();

    // softmax: 32 rows, 8 warps -> 4 rows each; exact softmax64 sequence
    for (int row = wrp; row < 32; row += 8) {
        const float* r = sD + row * 64;
        float a = r[lane];
        float b = r[lane + 32];
        float m = fmaxf(a, b);
        #pragma unroll
        for (int o = 16; o > 0; o >>= 1) m = fmaxf(m, __shfl_xor_sync(0xffffffffu, m, o));
        float e1 = __expf(a - m);
        float e2 = __expf(b - m);
        float s = e1 + e2;
        #pragma unroll
        for (int o = 16; o > 0; o >>= 1) s += __shfl_xor_sync(0xffffffffu, s, o);
        float inv = 1.0f / s;
        Db[row * 64 + lane]      = e1 * inv;
        Db[row * 64 + lane + 32] = e2 * inv;
    }
}

// ---------------------------------------------------------------------------
// fp32 SGEMM (U = attn @ Wv), tf32-rounded output. 64x64 tiles.
// ---------------------------------------------------------------------------
template <int BM, int BN, int BK, int TM, int TN, bool TRB, bool BIAS, bool CVTOUT>
__global__ void __launch_bounds__((BM / TM) * (BN / TN))
sgemm(const float* __restrict__ A0, const float* __restrict__ B0,
      float* __restrict__ C0, const float* __restrict__ bias,
      int M, int N, int K,
      long long sA1, long long sA2, long long sB1, long long sB2,
      long long sC1, long long sC2, int B2, float alpha)
{
    constexpr int THREADS = (BM / TM) * (BN / TN);
    constexpr int A_TRIPS = (BM * BK / 4) / THREADS;
    constexpr int B_TRIPS = (BN * BK / 4) / THREADS;

    int z = blockIdx.z;
    int i1 = z / B2;
    int i2 = z - i1 * B2;
    const float* A  = A0 + (size_t)i1 * sA1 + (size_t)i2 * sA2;
    const float* Bp = B0 + (size_t)i1 * sB1 + (size_t)i2 * sB2;
    float*       Cp = C0 + (size_t)i1 * sC1 + (size_t)i2 * sC2;

    __shared__ float As[BK][BM + 4];
    __shared__ float Bs[BK][BN + 4];

    const int tid = threadIdx.x;
    const int tn  = tid % (BN / TN);
    const int tm  = tid / (BN / TN);
    const int rowC = blockIdx.y * BM + tm * TM;
    const int colC = blockIdx.x * BN + tn * TN;

    float acc[TM][TN] = {};

    for (int k0 = 0; k0 < K; k0 += BK) {
        #pragma unroll
        for (int it = 0; it < A_TRIPS; it++) {
            int t  = tid + it * THREADS;
            int r  = t / (BK / 4);
            int c4 = (t % (BK / 4)) * 4;
            float4 v = *reinterpret_cast<const float4*>(
                A + (size_t)(blockIdx.y * BM + r) * K + k0 + c4);
            As[c4 + 0][r] = v.x; As[c4 + 1][r] = v.y;
            As[c4 + 2][r] = v.z; As[c4 + 3][r] = v.w;
        }
        if (TRB) {
            #pragma unroll
            for (int it = 0; it < B_TRIPS; it++) {
                int t  = tid + it * THREADS;
                int r  = t / (BK / 4);
                int c4 = (t % (BK / 4)) * 4;
                float4 v = *reinterpret_cast<const float4*>(
                    Bp + (size_t)(blockIdx.x * BN + r) * K + k0 + c4);
                Bs[c4 + 0][r] = v.x; Bs[c4 + 1][r] = v.y;
                Bs[c4 + 2][r] = v.z; Bs[c4 + 3][r] = v.w;
            }
        } else {
            #pragma unroll
            for (int it = 0; it < B_TRIPS; it++) {
                int t  = tid + it * THREADS;
                int r  = t / (BN / 4);
                int c4 = (t % (BN / 4)) * 4;
                float4 v = *reinterpret_cast<const float4*>(
                    Bp + (size_t)(k0 + r) * N + blockIdx.x * BN + c4);
                *reinterpret_cast<float4*>(&Bs[r][c4]) = v;
            }
        }
        __syncthreads();

        #pragma unroll
        for (int k = 0; k < BK; k++) {
            float ra[TM], rb[TN];
            #pragma unroll
            for (int i = 0; i < TM; i++) ra[i] = As[k][tm * TM + i];
            #pragma unroll
            for (int j = 0; j < TN; j++) rb[j] = Bs[k][tn * TN + j];
            #pragma unroll
            for (int i = 0; i < TM; i++)
                #pragma unroll
                for (int j = 0; j < TN; j++)
                    acc[i][j] = fmaf(ra[i], rb[j], acc[i][j]);
        }
        __syncthreads();
    }

    #pragma unroll
    for (int i = 0; i < TM; i++) {
        float bv = BIAS ? bias[rowC + i] : 0.0f;
        #pragma unroll
        for (int j = 0; j < TN; j++) {
            float v = alpha * acc[i][j] + bv;
            if (CVTOUT) v = __uint_as_float(f2tf(v));
            Cp[(size_t)(rowC + i) * N + colC + j] = v;
        }
    }
}

extern "C" void kernel_launch(void* const* d_in, const int* in_sizes, int n_in,
                              void* d_out, int out_size)
{
    const float* f_m  = (const float*)d_in[0];
    const float* f_n  = (const float*)d_in[1];
    const float* Wq   = (const float*)d_in[2];
    const float* Wkv  = (const float*)d_in[3];
    const float* Wout = (const float*)d_in[4];
    const float* bout = (const float*)d_in[5];
    float* out = (float*)d_out;

    float *G, *T, *dots, *U, *Mm, *cm, *cn, *cWk, *cWout;
    cudaGetSymbolAddress((void**)&G,     g_G);
    cudaGetSymbolAddress((void**)&T,     g_T);
    cudaGetSymbolAddress((void**)&dots,  g_dots);
    cudaGetSymbolAddress((void**)&U,     g_U);
    cudaGetSymbolAddress((void**)&Mm,    g_M);
    cudaGetSymbolAddress((void**)&cm,    g_cm);
    cudaGetSymbolAddress((void**)&cn,    g_cn);
    cudaGetSymbolAddress((void**)&cWk,   g_cWk);
    cudaGetSymbolAddress((void**)&cWout, g_cWout);

    const long long CF  = (long long)CDIM * NSP;
    const long long CC  = (long long)CDIM * CDIM;
    const long long THD = (long long)CDIM * DH;

    constexpr int SM_128_NT = (2 * 128 * 36 + 2 * 128 * 36) * 4;   // 73728
    constexpr int SM_64_NT  = (2 * 64 * 36 + 2 * 64 * 36) * 4;     // 36864
    constexpr int SM_128_NN = (2 * 128 * 36 + 2 * 32 * 136) * 4;   // 71680
    constexpr int SM_256_NN = (2 * 256 * 36 + 2 * 32 * 136) * 4;   // 108544

    cudaFuncSetAttribute(tf32gemm_ca<128, 128, 2, 4, true, false, true>,
                         cudaFuncAttributeMaxDynamicSharedMemorySize, SM_128_NT);
    cudaFuncSetAttribute(tf32gemm_ca<64, 64, 2, 4, true, false, false>,
                         cudaFuncAttributeMaxDynamicSharedMemorySize, SM_64_NT);
    cudaFuncSetAttribute(tf32gemm_ca<128, 128, 2, 4, false, false, true>,
                         cudaFuncAttributeMaxDynamicSharedMemorySize, SM_128_NN);
    cudaFuncSetAttribute(tf32gemm_ca<256, 128, 4, 2, false, true, false>,
                         cudaFuncAttributeMaxDynamicSharedMemorySize, SM_256_NN);

    // 0) all tf32 pre-conversions in ONE launch
    {
        const int NB = BATCH * CDIM * NSP / 4;     // 4194304
        const int NW = CDIM * CDIM / 4;            // 65536
        int total = 2 * NB + 2 * NW;               // 8519680 = 33280*256
        cvt_all_k<<<total / 256, 256>>>(
            (const float4*)f_m, (uint4*)cm, (const float4*)f_n, (uint4*)cn,
            (const float4*)Wkv, (uint4*)cWk, (const float4*)Wout, (uint4*)cWout);
    }

    // 1) G[b] = cm[b] @ cn[b]^T   (NT, K=4096), out tf32-rounded
    tf32gemm_ca<128, 128, 2, 4, true, false, true>
        <<<dim3(4, 4, BATCH), 256, SM_128_NT>>>(
        cm, cn, G, nullptr, CDIM, CDIM, NSP,
        CF, 0, CF, 0, CC, 0, 1, 1.0f);

    // 2) T[b,h] = G[b] @ cWk_h^T  (NT, K=512), out fp32
    tf32gemm_ca<64, 64, 2, 4, true, false, false>
        <<<dim3(1, 8, BATCH * NHEADS), 256, SM_64_NT>>>(
        G, cWk, T, nullptr, CDIM, DH, CDIM,
        CC, 0, 0, (long long)DH * CDIM, (long long)NHEADS * THD, THD,
        NHEADS, 1.0f);

    // 3-4) dots + softmax fused (grid 2x64 = 128 CTAs) -> attn in `dots`
    dots_sm<<<dim3(2, BATCH * NHEADS), 256>>>(Wq, T, dots);

    // 5) U[b] = attn[b,h] @ Wv_h  (NN, K=64), 512 CTAs, out tf32-rounded
    sgemm<64, 64, 16, 4, 4, false, false, true>
        <<<dim3(8, 1, BATCH * NHEADS), 256>>>(
        dots, Wkv + (size_t)CDIM * CDIM, U, nullptr, DH, CDIM, DH,
        (long long)NHEADS * DH * DH, (long long)DH * DH,
        0, (long long)DH * CDIM,
        CC, (long long)DH * CDIM,
        NHEADS, 1.0f);

    // 6) M[b] = cWout @ U[b]   (NN, K=512), out tf32-rounded
    tf32gemm_ca<128, 128, 2, 4, false, false, true>
        <<<dim3(4, 4, BATCH), 256, SM_128_NN>>>(
        cWout, U, Mm, nullptr, CDIM, CDIM, CDIM,
        0, 0, CC, 0, CC, 0, 1, 1.0f);

    // 7) out[b] = M[b] @ cn[b] + bout  (NN, K=512, bias), 256x128 tiles
    tf32gemm_ca<256, 128, 4, 2, false, true, false>
        <<<dim3(32, 2, BATCH), 256, SM_256_NN>>>(
        Mm, cn, out, bout, CDIM, NSP, CDIM,
        CC, 0, CF, 0, CF, 0, 1, 1.0f);
}

// round 15
// speedup vs baseline: 1.0393x; 1.0048x over previous
#include <cuda_runtime.h>

// CrossAttention_5385888989393 — reduced channel-attention, TF32 tensor cores.
// R14: best-measured components. cvt 4-way fused; GEMM1 pure cp.async (CVTA
// reverted); middle = dots(128 CTAs, softmax fused in epilogue) + U sgemm;
// GEMM7 256x128. Numerics bit-identical (rel_err 6.493987e-4).

#define BATCH 8
#define NHEADS 8
#define DH 64
#define CDIM 512
#define NSP 4096

__device__ float g_G[BATCH * CDIM * CDIM];
__device__ float g_T[BATCH * NHEADS * CDIM * DH];
__device__ float g_dots[BATCH * NHEADS * DH * DH];
__device__ float g_U[BATCH * CDIM * CDIM];
__device__ float g_M[BATCH * CDIM * CDIM];
__device__ float g_cm[BATCH * CDIM * NSP];     // tf32(f_m)
__device__ float g_cn[BATCH * CDIM * NSP];     // tf32(f_n)
__device__ float g_cWk[CDIM * CDIM];           // tf32(Wkv k-half)
__device__ float g_cWout[CDIM * CDIM];         // tf32(Wout)

__device__ __forceinline__ unsigned f2tf(float f) {
    unsigned u;
    asm("cvt.rna.tf32.f32 %0, %1;" : "=r"(u) : "f"(f));
    return u;
}

__device__ __forceinline__ void cp16(void* sdst, const void* gsrc) {
    unsigned s = (unsigned)__cvta_generic_to_shared(sdst);
    asm volatile("cp.async.cg.shared.global [%0], [%1], 16;\n" :: "r"(s), "l"(gsrc));
}
__device__ __forceinline__ void cp_commit() {
    asm volatile("cp.async.commit_group;\n");
}

// ---------------------------------------------------------------------------
// Fused tf32 conversion of all four operands in one launch.
// ---------------------------------------------------------------------------
__global__ void cvt_all_k(const float4* __restrict__ fm, uint4* __restrict__ cm,
                          const float4* __restrict__ fn, uint4* __restrict__ cn,
                          const float4* __restrict__ wkv, uint4* __restrict__ cwk,
                          const float4* __restrict__ wout, uint4* __restrict__ cwout)
{
    const int NB = BATCH * CDIM * NSP / 4;   // 4194304
    const int NW = CDIM * CDIM / 4;          // 65536
    int i = blockIdx.x * blockDim.x + threadIdx.x;
    const float4* src; uint4* dst; int off;
    if (i < NB)               { src = fm;   dst = cm;    off = i; }
    else if (i < 2 * NB)      { src = fn;   dst = cn;    off = i - NB; }
    else if (i < 2 * NB + NW) { src = wkv;  dst = cwk;   off = i - 2 * NB; }
    else                      { src = wout; dst = cwout; off = i - 2 * NB - NW; }
    float4 v = src[off];
    uint4 o;
    o.x = f2tf(v.x); o.y = f2tf(v.y); o.z = f2tf(v.z); o.w = f2tf(v.w);
    dst[off] = o;
}

// ---------------------------------------------------------------------------
// cp.async-fed TF32 GEMM (operands pre-rounded tf32 in gmem).
//   BK=32, 2-stage smem double buffer, 256 threads = 8 warps (WRR x WCC).
// ---------------------------------------------------------------------------
template <int BM, int BN, int WRR, int WCC, bool TRB, bool BIAS, bool CVTOUT>
__global__ void __launch_bounds__(256)
tf32gemm_ca(const float* __restrict__ A0, const float* __restrict__ B0,
            float* __restrict__ C0, const float* __restrict__ bias,
            int M, int N, int K,
            long long sA1, long long sA2, long long sB1, long long sB2,
            long long sC1, long long sC2, int B2, float alpha)
{
    constexpr int BK = 32;
    constexpr int WM = BM / WRR;
    constexpr int WN = BN / WCC;
    constexpr int IT = WM / 16;
    constexpr int JT = WN / 8;
    static_assert(WRR * WCC == 8, "8 warps");

    constexpr int AW  = BK + 4;
    constexpr int BSR = TRB ? BN : BK;
    constexpr int BSC = TRB ? (BK + 4) : (BN + 8);
    constexpr int A_WORDS = BM * AW;
    constexpr int B_WORDS = BSR * BSC;

    constexpr int A_T4   = (BM * (BK / 4)) / 256;
    constexpr int BT_T4  = (BN * (BK / 4)) / 256;
    constexpr int BNN_T4 = (BK * (BN / 4)) / 256;
    constexpr int B_T4   = TRB ? BT_T4 : BNN_T4;

    extern __shared__ unsigned sm[];
    unsigned* Asm = sm;
    unsigned* Bsm = sm + 2 * A_WORDS;

    int z = blockIdx.z;
    int i1 = z / B2, i2 = z - i1 * B2;
    const float* A  = A0 + (size_t)i1 * sA1 + (size_t)i2 * sA2;
    const float* Bp = B0 + (size_t)i1 * sB1 + (size_t)i2 * sB2;
    float*       Cp = C0 + (size_t)i1 * sC1 + (size_t)i2 * sC2;

    const int tid  = threadIdx.x;
    const int lane = tid & 31;
    const int wid  = tid >> 5;
    const int wr   = wid / WCC;
    const int wc   = wid % WCC;
    const int g    = lane >> 2;
    const int tq   = lane & 3;

    const int rowBase = blockIdx.y * BM;
    const int colBase = blockIdx.x * BN;

    float c[IT][JT][4];
    #pragma unroll
    for (int i = 0; i < IT; i++)
        #pragma unroll
        for (int j = 0; j < JT; j++)
            c[i][j][0] = c[i][j][1] = c[i][j][2] = c[i][j][3] = 0.f;

    auto load_tile = [&](int s, int k0) {
        #pragma unroll
        for (int it = 0; it < A_T4; it++) {
            int t = tid + it * 256;
            int r = t >> 3, c4 = (t & 7) << 2;
            cp16(&Asm[s * A_WORDS + r * AW + c4],
                 A + (size_t)(rowBase + r) * K + k0 + c4);
        }
        if (TRB) {
            #pragma unroll
            for (int it = 0; it < B_T4; it++) {
                int t = tid + it * 256;
                int r = t >> 3, c4 = (t & 7) << 2;
                cp16(&Bsm[s * B_WORDS + r * BSC + c4],
                     Bp + (size_t)(colBase + r) * K + k0 + c4);
            }
        } else {
            #pragma unroll
            for (int it = 0; it < B_T4; it++) {
                int t = tid + it * 256;
                int r = t / (BN / 4), c4 = (t % (BN / 4)) << 2;
                cp16(&Bsm[s * B_WORDS + r * BSC + c4],
                     Bp + (size_t)(k0 + r) * N + colBase + c4);
            }
        }
        cp_commit();
    };

    load_tile(0, 0);

    int buf = 0;
    for (int k0 = 0; k0 < K; k0 += BK) {
        const bool has_next = (k0 + BK) < K;
        if (has_next) load_tile(buf ^ 1, k0 + BK);

        if (has_next) { asm volatile("cp.async.wait_group 1;\n"); }
        else          { asm volatile("cp.async.wait_group 0;\n"); }
        __syncthreads();

        const unsigned* Ab = Asm + buf * A_WORDS;
        const unsigned* Bb = Bsm + buf * B_WORDS;

        #pragma unroll
        for (int ks = 0; ks < BK; ks += 8) {
            unsigned a[IT][4], b[JT][2];
            #pragma unroll
            for (int i = 0; i < IT; i++) {
                int m = wr * WM + i * 16;
                a[i][0] = Ab[(m + g) * AW + ks + tq];
                a[i][1] = Ab[(m + g + 8) * AW + ks + tq];
                a[i][2] = Ab[(m + g) * AW + ks + tq + 4];
                a[i][3] = Ab[(m + g + 8) * AW + ks + tq + 4];
            }
            #pragma unroll
            for (int j = 0; j < JT; j++) {
                int n = wc * WN + j * 8;
                if (TRB) {
                    b[j][0] = Bb[(n + g) * BSC + ks + tq];
                    b[j][1] = Bb[(n + g) * BSC + ks + tq + 4];
                } else {
                    b[j][0] = Bb[(ks + tq) * BSC + n + g];
                    b[j][1] = Bb[(ks + tq + 4) * BSC + n + g];
                }
            }
            #pragma unroll
            for (int i = 0; i < IT; i++)
                #pragma unroll
                for (int j = 0; j < JT; j++)
                    asm volatile(
                        "mma.sync.aligned.m16n8k8.row.col.f32.tf32.tf32.f32 "
                        "{%0,%1,%2,%3}, {%4,%5,%6,%7}, {%8,%9}, {%0,%1,%2,%3};\n"
                        : "+f"(c[i][j][0]), "+f"(c[i][j][1]),
                          "+f"(c[i][j][2]), "+f"(c[i][j][3])
                        : "r"(a[i][0]), "r"(a[i][1]), "r"(a[i][2]), "r"(a[i][3]),
                          "r"(b[j][0]), "r"(b[j][1]));
        }
        __syncthreads();
        buf ^= 1;
    }

    #pragma unroll
    for (int i = 0; i < IT; i++) {
        int row = rowBase + wr * WM + i * 16 + g;
        float bv0 = BIAS ? bias[row] : 0.f;
        float bv1 = BIAS ? bias[row + 8] : 0.f;
        #pragma unroll
        for (int j = 0; j < JT; j++) {
            int col = colBase + wc * WN + j * 8 + 2 * tq;
            float v00 = alpha * c[i][j][0] + bv0;
            float v01 = alpha * c[i][j][1] + bv0;
            float v10 = alpha * c[i][j][2] + bv1;
            float v11 = alpha * c[i][j][3] + bv1;
            if (CVTOUT) {
                v00 = __uint_as_float(f2tf(v00));
                v01 = __uint_as_float(f2tf(v01));
                v10 = __uint_as_float(f2tf(v10));
                v11 = __uint_as_float(f2tf(v11));
            }
            Cp[(size_t)row * N + col]           = v00;
            Cp[(size_t)row * N + col + 1]       = v01;
            Cp[(size_t)(row + 8) * N + col]     = v10;
            Cp[(size_t)(row + 8) * N + col + 1] = v11;
        }
    }
}

// ---------------------------------------------------------------------------
// dots + softmax fused: one CTA computes a 32-row block of
//   dots = (Wq_h @ T_bh)*0.125  then softmax rows -> attn to gmem.
// grid (2, 64). Per-element K ascending; epilogue = 0.125*acc + 0.0f staged
// to smem; softmax op-sequence identical to softmax64 -> bit-identical.
// ---------------------------------------------------------------------------
__global__ void __launch_bounds__(256)
dots_sm(const float* __restrict__ Wq, const float* __restrict__ T,
        float* __restrict__ dots)
{
    const int z  = blockIdx.y;              // b*NHEADS + h
    const int h  = z % NHEADS;
    const int r0 = blockIdx.x * 32;
    const float* Aq = Wq + (size_t)h * DH * CDIM + (size_t)r0 * CDIM;  // 32x512
    const float* Tb = T  + (size_t)z * CDIM * DH;                      // 512x64
    float* Db = dots + (size_t)z * DH * DH + (size_t)r0 * 64;

    __shared__ float As[32][36];   // [k][m]
    __shared__ float Bs[32][68];   // [k][n]
    __shared__ float sD[32 * 64];  // staged dots

    const int tid  = threadIdx.x;
    const int tn   = tid & 15;     // col group (4 cols)
    const int tm   = tid >> 4;     // row group (2 rows)
    const int lane = tid & 31;
    const int wrp  = tid >> 5;

    float acc[2][4] = {};

    for (int k0 = 0; k0 < CDIM; k0 += 32) {
        {   // A tile 32x32 (K-contig), store transposed As[k][m]
            int r = tid >> 3, c4 = (tid & 7) << 2;
            float4 v = *(const float4*)(Aq + (size_t)r * CDIM + k0 + c4);
            As[c4 + 0][r] = v.x; As[c4 + 1][r] = v.y;
            As[c4 + 2][r] = v.z; As[c4 + 3][r] = v.w;
        }
        #pragma unroll
        for (int it = 0; it < 2; it++) {   // B tile 32k x 64n
            int t = tid + it * 256;
            int r = t >> 4, c4 = (t & 15) << 2;
            float4 v = *(const float4*)(Tb + (size_t)(k0 + r) * DH + c4);
            *reinterpret_cast<float4*>(&Bs[r][c4]) = v;
        }
        __syncthreads();

        #pragma unroll
        for (int k = 0; k < 32; k++) {
            float ra[2], rb[4];
            #pragma unroll
            for (int i = 0; i < 2; i++) ra[i] = As[k][tm * 2 + i];
            #pragma unroll
            for (int j = 0; j < 4; j++) rb[j] = Bs[k][tn * 4 + j];
            #pragma unroll
            for (int i = 0; i < 2; i++)
                #pragma unroll
                for (int j = 0; j < 4; j++)
                    acc[i][j] = fmaf(ra[i], rb[j], acc[i][j]);
        }
        __syncthreads();
    }

    // stage (identical to old epilogue: alpha*acc + 0.0f)
    #pragma unroll
    for (int i = 0; i < 2; i++)
        #pragma unroll
        for (int j = 0; j < 4; j++)
            sD[(tm * 2 + i) * 64 + tn * 4 + j] = 0.125f * acc[i][j] + 0.0f;
    __syncthreads();

    // softmax: 32 rows, 8 warps -> 4 rows each; exact softmax64 sequence
    for (int row = wrp; row < 32; row += 8) {
        const float* r = sD + row * 64;
        float a = r[lane];
        float b = r[lane + 32];
        float m = fmaxf(a, b);
        #pragma unroll
        for (int o = 16; o > 0; o >>= 1) m = fmaxf(m, __shfl_xor_sync(0xffffffffu, m, o));
        float e1 = __expf(a - m);
        float e2 = __expf(b - m);
        float s = e1 + e2;
        #pragma unroll
        for (int o = 16; o > 0; o >>= 1) s += __shfl_xor_sync(0xffffffffu, s, o);
        float inv = 1.0f / s;
        Db[row * 64 + lane]      = e1 * inv;
        Db[row * 64 + lane + 32] = e2 * inv;
    }
}

// ---------------------------------------------------------------------------
// fp32 SGEMM (U = attn @ Wv), tf32-rounded output. 64x64 tiles.
// ---------------------------------------------------------------------------
template <int BM, int BN, int BK, int TM, int TN, bool TRB, bool BIAS, bool CVTOUT>
__global__ void __launch_bounds__((BM / TM) * (BN / TN))
sgemm(const float* __restrict__ A0, const float* __restrict__ B0,
      float* __restrict__ C0, const float* __restrict__ bias,
      int M, int N, int K,
      long long sA1, long long sA2, long long sB1, long long sB2,
      long long sC1, long long sC2, int B2, float alpha)
{
    constexpr int THREADS = (BM / TM) * (BN / TN);
    constexpr int A_TRIPS = (BM * BK / 4) / THREADS;
    constexpr int B_TRIPS = (BN * BK / 4) / THREADS;

    int z = blockIdx.z;
    int i1 = z / B2;
    int i2 = z - i1 * B2;
    const float* A  = A0 + (size_t)i1 * sA1 + (size_t)i2 * sA2;
    const float* Bp = B0 + (size_t)i1 * sB1 + (size_t)i2 * sB2;
    float*       Cp = C0 + (size_t)i1 * sC1 + (size_t)i2 * sC2;

    __shared__ float As[BK][BM + 4];
    __shared__ float Bs[BK][BN + 4];

    const int tid = threadIdx.x;
    const int tn  = tid % (BN / TN);
    const int tm  = tid / (BN / TN);
    const int rowC = blockIdx.y * BM + tm * TM;
    const int colC = blockIdx.x * BN + tn * TN;

    float acc[TM][TN] = {};

    for (int k0 = 0; k0 < K; k0 += BK) {
        #pragma unroll
        for (int it = 0; it < A_TRIPS; it++) {
            int t  = tid + it * THREADS;
            int r  = t / (BK / 4);
            int c4 = (t % (BK / 4)) * 4;
            float4 v = *reinterpret_cast<const float4*>(
                A + (size_t)(blockIdx.y * BM + r) * K + k0 + c4);
            As[c4 + 0][r] = v.x; As[c4 + 1][r] = v.y;
            As[c4 + 2][r] = v.z; As[c4 + 3][r] = v.w;
        }
        if (TRB) {
            #pragma unroll
            for (int it = 0; it < B_TRIPS; it++) {
                int t  = tid + it * THREADS;
                int r  = t / (BK / 4);
                int c4 = (t % (BK / 4)) * 4;
                float4 v = *reinterpret_cast<const float4*>(
                    Bp + (size_t)(blockIdx.x * BN + r) * K + k0 + c4);
                Bs[c4 + 0][r] = v.x; Bs[c4 + 1][r] = v.y;
                Bs[c4 + 2][r] = v.z; Bs[c4 + 3][r] = v.w;
            }
        } else {
            #pragma unroll
            for (int it = 0; it < B_TRIPS; it++) {
                int t  = tid + it * THREADS;
                int r  = t / (BN / 4);
                int c4 = (t % (BN / 4)) * 4;
                float4 v = *reinterpret_cast<const float4*>(
                    Bp + (size_t)(k0 + r) * N + blockIdx.x * BN + c4);
                *reinterpret_cast<float4*>(&Bs[r][c4]) = v;
            }
        }
        __syncthreads();

        #pragma unroll
        for (int k = 0; k < BK; k++) {
            float ra[TM], rb[TN];
            #pragma unroll
            for (int i = 0; i < TM; i++) ra[i] = As[k][tm * TM + i];
            #pragma unroll
            for (int j = 0; j < TN; j++) rb[j] = Bs[k][tn * TN + j];
            #pragma unroll
            for (int i = 0; i < TM; i++)
                #pragma unroll
                for (int j = 0; j < TN; j++)
                    acc[i][j] = fmaf(ra[i], rb[j], acc[i][j]);
        }
        __syncthreads();
    }

    #pragma unroll
    for (int i = 0; i < TM; i++) {
        float bv = BIAS ? bias[rowC + i] : 0.0f;
        #pragma unroll
        for (int j = 0; j < TN; j++) {
            float v = alpha * acc[i][j] + bv;
            if (CVTOUT) v = __uint_as_float(f2tf(v));
            Cp[(size_t)(rowC + i) * N + colC + j] = v;
        }
    }
}

extern "C" void kernel_launch(void* const* d_in, const int* in_sizes, int n_in,
                              void* d_out, int out_size)
{
    const float* f_m  = (const float*)d_in[0];
    const float* f_n  = (const float*)d_in[1];
    const float* Wq   = (const float*)d_in[2];
    const float* Wkv  = (const float*)d_in[3];
    const float* Wout = (const float*)d_in[4];
    const float* bout = (const float*)d_in[5];
    float* out = (float*)d_out;

    float *G, *T, *dots, *U, *Mm, *cm, *cn, *cWk, *cWout;
    cudaGetSymbolAddress((void**)&G,     g_G);
    cudaGetSymbolAddress((void**)&T,     g_T);
    cudaGetSymbolAddress((void**)&dots,  g_dots);
    cudaGetSymbolAddress((void**)&U,     g_U);
    cudaGetSymbolAddress((void**)&Mm,    g_M);
    cudaGetSymbolAddress((void**)&cm,    g_cm);
    cudaGetSymbolAddress((void**)&cn,    g_cn);
    cudaGetSymbolAddress((void**)&cWk,   g_cWk);
    cudaGetSymbolAddress((void**)&cWout, g_cWout);

    const long long CF  = (long long)CDIM * NSP;
    const long long CC  = (long long)CDIM * CDIM;
    const long long THD = (long long)CDIM * DH;

    constexpr int SM_128_NT = (2 * 128 * 36 + 2 * 128 * 36) * 4;   // 73728
    constexpr int SM_64_NT  = (2 * 64 * 36 + 2 * 64 * 36) * 4;     // 36864
    constexpr int SM_128_NN = (2 * 128 * 36 + 2 * 32 * 136) * 4;   // 71680
    constexpr int SM_256_NN = (2 * 256 * 36 + 2 * 32 * 136) * 4;   // 108544

    cudaFuncSetAttribute(tf32gemm_ca<128, 128, 2, 4, true, false, true>,
                         cudaFuncAttributeMaxDynamicSharedMemorySize, SM_128_NT);
    cudaFuncSetAttribute(tf32gemm_ca<64, 64, 2, 4, true, false, false>,
                         cudaFuncAttributeMaxDynamicSharedMemorySize, SM_64_NT);
    cudaFuncSetAttribute(tf32gemm_ca<128, 128, 2, 4, false, false, true>,
                         cudaFuncAttributeMaxDynamicSharedMemorySize, SM_128_NN);
    cudaFuncSetAttribute(tf32gemm_ca<256, 128, 4, 2, false, true, false>,
                         cudaFuncAttributeMaxDynamicSharedMemorySize, SM_256_NN);

    // 0) all tf32 pre-conversions in ONE launch
    {
        const int NB = BATCH * CDIM * NSP / 4;     // 4194304
        const int NW = CDIM * CDIM / 4;            // 65536
        int total = 2 * NB + 2 * NW;               // 8519680 = 33280*256
        cvt_all_k<<<total / 256, 256>>>(
            (const float4*)f_m, (uint4*)cm, (const float4*)f_n, (uint4*)cn,
            (const float4*)Wkv, (uint4*)cWk, (const float4*)Wout, (uint4*)cWout);
    }

    // 1) G[b] = cm[b] @ cn[b]^T   (NT, K=4096), out tf32-rounded
    tf32gemm_ca<128, 128, 2, 4, true, false, true>
        <<<dim3(4, 4, BATCH), 256, SM_128_NT>>>(
        cm, cn, G, nullptr, CDIM, CDIM, NSP,
        CF, 0, CF, 0, CC, 0, 1, 1.0f);

    // 2) T[b,h] = G[b] @ cWk_h^T  (NT, K=512), out fp32
    tf32gemm_ca<64, 64, 2, 4, true, false, false>
        <<<dim3(1, 8, BATCH * NHEADS), 256, SM_64_NT>>>(
        G, cWk, T, nullptr, CDIM, DH, CDIM,
        CC, 0, 0, (long long)DH * CDIM, (long long)NHEADS * THD, THD,
        NHEADS, 1.0f);

    // 3-4) dots + softmax fused (grid 2x64 = 128 CTAs) -> attn in `dots`
    dots_sm<<<dim3(2, BATCH * NHEADS), 256>>>(Wq, T, dots);

    // 5) U[b] = attn[b,h] @ Wv_h  (NN, K=64), 512 CTAs, out tf32-rounded
    sgemm<64, 64, 16, 4, 4, false, false, true>
        <<<dim3(8, 1, BATCH * NHEADS), 256>>>(
        dots, Wkv + (size_t)CDIM * CDIM, U, nullptr, DH, CDIM, DH,
        (long long)NHEADS * DH * DH, (long long)DH * DH,
        0, (long long)DH * CDIM,
        CC, (long long)DH * CDIM,
        NHEADS, 1.0f);

    // 6) M[b] = cWout @ U[b]   (NN, K=512), out tf32-rounded
    tf32gemm_ca<128, 128, 2, 4, false, false, true>
        <<<dim3(4, 4, BATCH), 256, SM_128_NN>>>(
        cWout, U, Mm, nullptr, CDIM, CDIM, CDIM,
        0, 0, CC, 0, CC, 0, 1, 1.0f);

    // 7) out[b] = M[b] @ cn[b] + bout  (NN, K=512, bias), 256x128 tiles
    tf32gemm_ca<256, 128, 4, 2, false, true, false>
        <<<dim3(32, 2, BATCH), 256, SM_256_NN>>>(
        Mm, cn, out, bout, CDIM, NSP, CDIM,
        CC, 0, CF, 0, CF, 0, 1, 1.0f);
}

// round 16
// speedup vs baseline: 1.0657x; 1.0253x over previous
#include <cuda_runtime.h>

// CrossAttention_5385888989393 — reduced channel-attention, TF32 tensor cores.
// R16: two-stream batch-half pipeline (cvt overlaps compute); dots_sm double-
// buffered via cp.async; U sgemm single-iteration BK=64.
// Numerics bit-identical (rel_err 6.493987e-4).

#define BATCH 8
#define NHEADS 8
#define DH 64
#define CDIM 512
#define NSP 4096
#define HB (BATCH / 2)

__device__ float g_G[BATCH * CDIM * CDIM];
__device__ float g_T[BATCH * NHEADS * CDIM * DH];
__device__ float g_dots[BATCH * NHEADS * DH * DH];
__device__ float g_U[BATCH * CDIM * CDIM];
__device__ float g_M[BATCH * CDIM * CDIM];
__device__ float g_cm[BATCH * CDIM * NSP];
__device__ float g_cn[BATCH * CDIM * NSP];
__device__ float g_cWk[CDIM * CDIM];
__device__ float g_cWout[CDIM * CDIM];
__device__ float g_cWk2[CDIM * CDIM];
__device__ float g_cWout2[CDIM * CDIM];

__device__ __forceinline__ unsigned f2tf(float f) {
    unsigned u;
    asm("cvt.rna.tf32.f32 %0, %1;" : "=r"(u) : "f"(f));
    return u;
}

__device__ __forceinline__ void cp16(void* sdst, const void* gsrc) {
    unsigned s = (unsigned)__cvta_generic_to_shared(sdst);
    asm volatile("cp.async.cg.shared.global [%0], [%1], 16;\n" :: "r"(s), "l"(gsrc));
}
__device__ __forceinline__ void cp_commit() {
    asm volatile("cp.async.commit_group;\n");
}

// ---------------------------------------------------------------------------
// Half-batch tf32 conversion: f_m half, f_n half, plus private weight copies.
// ---------------------------------------------------------------------------
__global__ void cvt_half_k(const float4* __restrict__ fm, uint4* __restrict__ cm,
                           const float4* __restrict__ fn, uint4* __restrict__ cn,
                           const float4* __restrict__ wkv, uint4* __restrict__ cwk,
                           const float4* __restrict__ wout, uint4* __restrict__ cwout)
{
    const int NBH = HB * CDIM * NSP / 4;     // 2097152
    const int NW  = CDIM * CDIM / 4;         // 65536
    int i = blockIdx.x * blockDim.x + threadIdx.x;
    const float4* src; uint4* dst; int off;
    if (i < NBH)               { src = fm;   dst = cm;    off = i; }
    else if (i < 2 * NBH)      { src = fn;   dst = cn;    off = i - NBH; }
    else if (i < 2 * NBH + NW) { src = wkv;  dst = cwk;   off = i - 2 * NBH; }
    else                       { src = wout; dst = cwout; off = i - 2 * NBH - NW; }
    float4 v = src[off];
    uint4 o;
    o.x = f2tf(v.x); o.y = f2tf(v.y); o.z = f2tf(v.z); o.w = f2tf(v.w);
    dst[off] = o;
}

// ---------------------------------------------------------------------------
// cp.async-fed TF32 GEMM (operands pre-rounded tf32 in gmem). BK=32, 2-stage.
// ---------------------------------------------------------------------------
template <int BM, int BN, int WRR, int WCC, bool TRB, bool BIAS, bool CVTOUT>
__global__ void __launch_bounds__(256)
tf32gemm_ca(const float* __restrict__ A0, const float* __restrict__ B0,
            float* __restrict__ C0, const float* __restrict__ bias,
            int M, int N, int K,
            long long sA1, long long sA2, long long sB1, long long sB2,
            long long sC1, long long sC2, int B2, float alpha)
{
    constexpr int BK = 32;
    constexpr int WM = BM / WRR;
    constexpr int WN = BN / WCC;
    constexpr int IT = WM / 16;
    constexpr int JT = WN / 8;
    static_assert(WRR * WCC == 8, "8 warps");

    constexpr int AW  = BK + 4;
    constexpr int BSR = TRB ? BN : BK;
    constexpr int BSC = TRB ? (BK + 4) : (BN + 8);
    constexpr int A_WORDS = BM * AW;
    constexpr int B_WORDS = BSR * BSC;

    constexpr int A_T4   = (BM * (BK / 4)) / 256;
    constexpr int BT_T4  = (BN * (BK / 4)) / 256;
    constexpr int BNN_T4 = (BK * (BN / 4)) / 256;
    constexpr int B_T4   = TRB ? BT_T4 : BNN_T4;

    extern __shared__ unsigned sm[];
    unsigned* Asm = sm;
    unsigned* Bsm = sm + 2 * A_WORDS;

    int z = blockIdx.z;
    int i1 = z / B2, i2 = z - i1 * B2;
    const float* A  = A0 + (size_t)i1 * sA1 + (size_t)i2 * sA2;
    const float* Bp = B0 + (size_t)i1 * sB1 + (size_t)i2 * sB2;
    float*       Cp = C0 + (size_t)i1 * sC1 + (size_t)i2 * sC2;

    const int tid  = threadIdx.x;
    const int lane = tid & 31;
    const int wid  = tid >> 5;
    const int wr   = wid / WCC;
    const int wc   = wid % WCC;
    const int g    = lane >> 2;
    const int tq   = lane & 3;

    const int rowBase = blockIdx.y * BM;
    const int colBase = blockIdx.x * BN;

    float c[IT][JT][4];
    #pragma unroll
    for (int i = 0; i < IT; i++)
        #pragma unroll
        for (int j = 0; j < JT; j++)
            c[i][j][0] = c[i][j][1] = c[i][j][2] = c[i][j][3] = 0.f;

    auto load_tile = [&](int s, int k0) {
        #pragma unroll
        for (int it = 0; it < A_T4; it++) {
            int t = tid + it * 256;
            int r = t >> 3, c4 = (t & 7) << 2;
            cp16(&Asm[s * A_WORDS + r * AW + c4],
                 A + (size_t)(rowBase + r) * K + k0 + c4);
        }
        if (TRB) {
            #pragma unroll
            for (int it = 0; it < B_T4; it++) {
                int t = tid + it * 256;
                int r = t >> 3, c4 = (t & 7) << 2;
                cp16(&Bsm[s * B_WORDS + r * BSC + c4],
                     Bp + (size_t)(colBase + r) * K + k0 + c4);
            }
        } else {
            #pragma unroll
            for (int it = 0; it < B_T4; it++) {
                int t = tid + it * 256;
                int r = t / (BN / 4), c4 = (t % (BN / 4)) << 2;
                cp16(&Bsm[s * B_WORDS + r * BSC + c4],
                     Bp + (size_t)(k0 + r) * N + colBase + c4);
            }
        }
        cp_commit();
    };

    load_tile(0, 0);

    int buf = 0;
    for (int k0 = 0; k0 < K; k0 += BK) {
        const bool has_next = (k0 + BK) < K;
        if (has_next) load_tile(buf ^ 1, k0 + BK);

        if (has_next) { asm volatile("cp.async.wait_group 1;\n"); }
        else          { asm volatile("cp.async.wait_group 0;\n"); }
        __syncthreads();

        const unsigned* Ab = Asm + buf * A_WORDS;
        const unsigned* Bb = Bsm + buf * B_WORDS;

        #pragma unroll
        for (int ks = 0; ks < BK; ks += 8) {
            unsigned a[IT][4], b[JT][2];
            #pragma unroll
            for (int i = 0; i < IT; i++) {
                int m = wr * WM + i * 16;
                a[i][0] = Ab[(m + g) * AW + ks + tq];
                a[i][1] = Ab[(m + g + 8) * AW + ks + tq];
                a[i][2] = Ab[(m + g) * AW + ks + tq + 4];
                a[i][3] = Ab[(m + g + 8) * AW + ks + tq + 4];
            }
            #pragma unroll
            for (int j = 0; j < JT; j++) {
                int n = wc * WN + j * 8;
                if (TRB) {
                    b[j][0] = Bb[(n + g) * BSC + ks + tq];
                    b[j][1] = Bb[(n + g) * BSC + ks + tq + 4];
                } else {
                    b[j][0] = Bb[(ks + tq) * BSC + n + g];
                    b[j][1] = Bb[(ks + tq + 4) * BSC + n + g];
                }
            }
            #pragma unroll
            for (int i = 0; i < IT; i++)
                #pragma unroll
                for (int j = 0; j < JT; j++)
                    asm volatile(
                        "mma.sync.aligned.m16n8k8.row.col.f32.tf32.tf32.f32 "
                        "{%0,%1,%2,%3}, {%4,%5,%6,%7}, {%8,%9}, {%0,%1,%2,%3};\n"
                        : "+f"(c[i][j][0]), "+f"(c[i][j][1]),
                          "+f"(c[i][j][2]), "+f"(c[i][j][3])
                        : "r"(a[i][0]), "r"(a[i][1]), "r"(a[i][2]), "r"(a[i][3]),
                          "r"(b[j][0]), "r"(b[j][1]));
        }
        __syncthreads();
        buf ^= 1;
    }

    #pragma unroll
    for (int i = 0; i < IT; i++) {
        int row = rowBase + wr * WM + i * 16 + g;
        float bv0 = BIAS ? bias[row] : 0.f;
        float bv1 = BIAS ? bias[row + 8] : 0.f;
        #pragma unroll
        for (int j = 0; j < JT; j++) {
            int col = colBase + wc * WN + j * 8 + 2 * tq;
            float v00 = alpha * c[i][j][0] + bv0;
            float v01 = alpha * c[i][j][1] + bv0;
            float v10 = alpha * c[i][j][2] + bv1;
            float v11 = alpha * c[i][j][3] + bv1;
            if (CVTOUT) {
                v00 = __uint_as_float(f2tf(v00));
                v01 = __uint_as_float(f2tf(v01));
                v10 = __uint_as_float(f2tf(v10));
                v11 = __uint_as_float(f2tf(v11));
            }
            Cp[(size_t)row * N + col]           = v00;
            Cp[(size_t)row * N + col + 1]       = v01;
            Cp[(size_t)(row + 8) * N + col]     = v10;
            Cp[(size_t)(row + 8) * N + col + 1] = v11;
        }
    }
}

// ---------------------------------------------------------------------------
// dots + softmax fused, cp.async double-buffered. CTA = 32-row block of
//   dots = (Wq_h @ T_bh)*0.125 -> softmax -> attn to gmem.  grid (2, zcount).
// A kept row-major [m][k] (per-warp reads are 4-address broadcasts, no
// conflicts); per-element K ascending; softmax sequence identical.
// ---------------------------------------------------------------------------
__global__ void __launch_bounds__(256)
dots_sm_db(const float* __restrict__ Wq, const float* __restrict__ T,
           float* __restrict__ dots)
{
    const int z  = blockIdx.y;              // local (b,h) index
    const int h  = z % NHEADS;
    const int r0 = blockIdx.x * 32;
    const float* Aq = Wq + (size_t)h * DH * CDIM + (size_t)r0 * CDIM;  // 32x512
    const float* Tb = T  + (size_t)z * CDIM * DH;                      // 512x64
    float* Db = dots + (size_t)z * DH * DH + (size_t)r0 * 64;

    __shared__ float As[2][32][36];   // [m][k] rows
    __shared__ float Bs[2][32][68];   // [k][n] rows
    __shared__ float sD[32 * 64];

    const int tid  = threadIdx.x;
    const int tn   = tid & 15;
    const int tm   = tid >> 4;
    const int lane = tid & 31;
    const int wrp  = tid >> 5;

    auto load_tile = [&](int s, int k0) {
        {   // A: 32 rows x 128B -> 256 cp16, 1/thread
            int r = tid >> 3, c4 = (tid & 7) << 2;
            cp16(&As[s][r][c4], Aq + (size_t)r * CDIM + k0 + c4);
        }
        #pragma unroll
        for (int it = 0; it < 2; it++) {   // B: 32 rows x 256B -> 512 cp16
            int t = tid + it * 256;
            int r = t >> 4, c4 = (t & 15) << 2;
            cp16(&Bs[s][r][c4], Tb + (size_t)(k0 + r) * DH + c4);
        }
        cp_commit();
    };

    float acc[2][4] = {};

    load_tile(0, 0);
    int buf = 0;
    for (int k0 = 0; k0 < CDIM; k0 += 32) {
        const bool has_next = (k0 + 32) < CDIM;
        if (has_next) load_tile(buf ^ 1, k0 + 32);

        if (has_next) { asm volatile("cp.async.wait_group 1;\n"); }
        else          { asm volatile("cp.async.wait_group 0;\n"); }
        __syncthreads();

        #pragma unroll
        for (int k = 0; k < 32; k++) {
            float ra[2], rb[4];
            #pragma unroll
            for (int i = 0; i < 2; i++) ra[i] = As[buf][tm * 2 + i][k];
            #pragma unroll
            for (int j = 0; j < 4; j++) rb[j] = Bs[buf][k][tn * 4 + j];
            #pragma unroll
            for (int i = 0; i < 2; i++)
                #pragma unroll
                for (int j = 0; j < 4; j++)
                    acc[i][j] = fmaf(ra[i], rb[j], acc[i][j]);
        }
        __syncthreads();
        buf ^= 1;
    }

    #pragma unroll
    for (int i = 0; i < 2; i++)
        #pragma unroll
        for (int j = 0; j < 4; j++)
            sD[(tm * 2 + i) * 64 + tn * 4 + j] = 0.125f * acc[i][j] + 0.0f;
    __syncthreads();

    for (int row = wrp; row < 32; row += 8) {
        const float* r = sD + row * 64;
        float a = r[lane];
        float b = r[lane + 32];
        float m = fmaxf(a, b);
        #pragma unroll
        for (int o = 16; o > 0; o >>= 1) m = fmaxf(m, __shfl_xor_sync(0xffffffffu, m, o));
        float e1 = __expf(a - m);
        float e2 = __expf(b - m);
        float s = e1 + e2;
        #pragma unroll
        for (int o = 16; o > 0; o >>= 1) s += __shfl_xor_sync(0xffffffffu, s, o);
        float inv = 1.0f / s;
        Db[row * 64 + lane]      = e1 * inv;
        Db[row * 64 + lane + 32] = e2 * inv;
    }
}

// ---------------------------------------------------------------------------
// fp32 SGEMM (U = attn @ Wv), tf32-rounded output.
// ---------------------------------------------------------------------------
template <int BM, int BN, int BK, int TM, int TN, bool TRB, bool BIAS, bool CVTOUT>
__global__ void __launch_bounds__((BM / TM) * (BN / TN))
sgemm(const float* __restrict__ A0, const float* __restrict__ B0,
      float* __restrict__ C0, const float* __restrict__ bias,
      int M, int N, int K,
      long long sA1, long long sA2, long long sB1, long long sB2,
      long long sC1, long long sC2, int B2, float alpha)
{
    constexpr int THREADS = (BM / TM) * (BN / TN);
    constexpr int A_TRIPS = (BM * BK / 4) / THREADS;
    constexpr int B_TRIPS = (BN * BK / 4) / THREADS;

    int z = blockIdx.z;
    int i1 = z / B2;
    int i2 = z - i1 * B2;
    const float* A  = A0 + (size_t)i1 * sA1 + (size_t)i2 * sA2;
    const float* Bp = B0 + (size_t)i1 * sB1 + (size_t)i2 * sB2;
    float*       Cp = C0 + (size_t)i1 * sC1 + (size_t)i2 * sC2;

    __shared__ float As[BK][BM + 4];
    __shared__ float Bs[BK][BN + 4];

    const int tid = threadIdx.x;
    const int tn  = tid % (BN / TN);
    const int tm  = tid / (BN / TN);
    const int rowC = blockIdx.y * BM + tm * TM;
    const int colC = blockIdx.x * BN + tn * TN;

    float acc[TM][TN] = {};

    for (int k0 = 0; k0 < K; k0 += BK) {
        #pragma unroll
        for (int it = 0; it < A_TRIPS; it++) {
            int t  = tid + it * THREADS;
            int r  = t / (BK / 4);
            int c4 = (t % (BK / 4)) * 4;
            float4 v = *reinterpret_cast<const float4*>(
                A + (size_t)(blockIdx.y * BM + r) * K + k0 + c4);
            As[c4 + 0][r] = v.x; As[c4 + 1][r] = v.y;
            As[c4 + 2][r] = v.z; As[c4 + 3][r] = v.w;
        }
        if (TRB) {
            #pragma unroll
            for (int it = 0; it < B_TRIPS; it++) {
                int t  = tid + it * THREADS;
                int r  = t / (BK / 4);
                int c4 = (t % (BK / 4)) * 4;
                float4 v = *reinterpret_cast<const float4*>(
                    Bp + (size_t)(blockIdx.x * BN + r) * K + k0 + c4);
                Bs[c4 + 0][r] = v.x; Bs[c4 + 1][r] = v.y;
                Bs[c4 + 2][r] = v.z; Bs[c4 + 3][r] = v.w;
            }
        } else {
            #pragma unroll
            for (int it = 0; it < B_TRIPS; it++) {
                int t  = tid + it * THREADS;
                int r  = t / (BN / 4);
                int c4 = (t % (BN / 4)) * 4;
                float4 v = *reinterpret_cast<const float4*>(
                    Bp + (size_t)(k0 + r) * N + blockIdx.x * BN + c4);
                *reinterpret_cast<float4*>(&Bs[r][c4]) = v;
            }
        }
        __syncthreads();

        #pragma unroll
        for (int k = 0; k < BK; k++) {
            float ra[TM], rb[TN];
            #pragma unroll
            for (int i = 0; i < TM; i++) ra[i] = As[k][tm * TM + i];
            #pragma unroll
            for (int j = 0; j < TN; j++) rb[j] = Bs[k][tn * TN + j];
            #pragma unroll
            for (int i = 0; i < TM; i++)
                #pragma unroll
                for (int j = 0; j < TN; j++)
                    acc[i][j] = fmaf(ra[i], rb[j], acc[i][j]);
        }
        __syncthreads();
    }

    #pragma unroll
    for (int i = 0; i < TM; i++) {
        float bv = BIAS ? bias[rowC + i] : 0.0f;
        #pragma unroll
        for (int j = 0; j < TN; j++) {
            float v = alpha * acc[i][j] + bv;
            if (CVTOUT) v = __uint_as_float(f2tf(v));
            Cp[(size_t)(rowC + i) * N + colC + j] = v;
        }
    }
}

extern "C" void kernel_launch(void* const* d_in, const int* in_sizes, int n_in,
                              void* d_out, int out_size)
{
    const float* f_m  = (const float*)d_in[0];
    const float* f_n  = (const float*)d_in[1];
    const float* Wq   = (const float*)d_in[2];
    const float* Wkv  = (const float*)d_in[3];
    const float* Wout = (const float*)d_in[4];
    const float* bout = (const float*)d_in[5];
    float* out = (float*)d_out;

    float *G, *T, *dots, *U, *Mm, *cm, *cn, *cWk, *cWout, *cWk2, *cWout2;
    cudaGetSymbolAddress((void**)&G,      g_G);
    cudaGetSymbolAddress((void**)&T,      g_T);
    cudaGetSymbolAddress((void**)&dots,   g_dots);
    cudaGetSymbolAddress((void**)&U,      g_U);
    cudaGetSymbolAddress((void**)&Mm,     g_M);
    cudaGetSymbolAddress((void**)&cm,     g_cm);
    cudaGetSymbolAddress((void**)&cn,     g_cn);
    cudaGetSymbolAddress((void**)&cWk,    g_cWk);
    cudaGetSymbolAddress((void**)&cWout,  g_cWout);
    cudaGetSymbolAddress((void**)&cWk2,   g_cWk2);
    cudaGetSymbolAddress((void**)&cWout2, g_cWout2);

    const long long CF  = (long long)CDIM * NSP;
    const long long CC  = (long long)CDIM * CDIM;
    const long long THD = (long long)CDIM * DH;

    constexpr int SM_128_NT = (2 * 128 * 36 + 2 * 128 * 36) * 4;   // 73728
    constexpr int SM_64_NT  = (2 * 64 * 36 + 2 * 64 * 36) * 4;     // 36864
    constexpr int SM_128_NN = (2 * 128 * 36 + 2 * 32 * 136) * 4;   // 71680
    constexpr int SM_256_NN = (2 * 256 * 36 + 2 * 32 * 136) * 4;   // 108544

    cudaFuncSetAttribute(tf32gemm_ca<128, 128, 2, 4, true, false, true>,
                         cudaFuncAttributeMaxDynamicSharedMemorySize, SM_128_NT);
    cudaFuncSetAttribute(tf32gemm_ca<64, 64, 2, 4, true, false, false>,
                         cudaFuncAttributeMaxDynamicSharedMemorySize, SM_64_NT);
    cudaFuncSetAttribute(tf32gemm_ca<128, 128, 2, 4, false, false, true>,
                         cudaFuncAttributeMaxDynamicSharedMemorySize, SM_128_NN);
    cudaFuncSetAttribute(tf32gemm_ca<256, 128, 4, 2, false, true, false>,
                         cudaFuncAttributeMaxDynamicSharedMemorySize, SM_256_NN);

    // Fork-join: s0 runs half 0; s2 (after half-0 cvt) runs half 1.
    cudaStream_t s2;
    cudaStreamCreateWithFlags(&s2, cudaStreamNonBlocking);
    cudaEvent_t eFork, eJoin;
    cudaEventCreateWithFlags(&eFork, cudaEventDisableTiming);
    cudaEventCreateWithFlags(&eJoin, cudaEventDisableTiming);

    const int CVT_BLKS = (2 * (HB * CDIM * NSP / 4) + 2 * (CDIM * CDIM / 4)) / 256;

    for (int half = 0; half < 2; half++) {
        cudaStream_t st = half ? s2 : (cudaStream_t)0;
        const int b0 = half * HB;
        const float* fm_h = f_m + (size_t)b0 * CF;
        const float* fn_h = f_n + (size_t)b0 * CF;
        float* cm_h  = cm  + (size_t)b0 * CF;
        float* cn_h  = cn  + (size_t)b0 * CF;
        float* G_h   = G   + (size_t)b0 * CC;
        float* T_h   = T   + (size_t)b0 * NHEADS * THD;
        float* d_h   = dots + (size_t)b0 * NHEADS * DH * DH;
        float* U_h   = U   + (size_t)b0 * CC;
        float* M_h   = Mm  + (size_t)b0 * CC;
        float* out_h = out + (size_t)b0 * CF;
        float* wk_h  = half ? cWk2   : cWk;
        float* wo_h  = half ? cWout2 : cWout;

        // cvt for this half
        cvt_half_k<<<CVT_BLKS, 256, 0, st>>>(
            (const float4*)fm_h, (uint4*)cm_h, (const float4*)fn_h, (uint4*)cn_h,
            (const float4*)Wkv, (uint4*)wk_h, (const float4*)Wout, (uint4*)wo_h);

        if (half == 0) {   // release half 1 once half 0's cvt is queued
            cudaEventRecord(eFork, 0);
            cudaStreamWaitEvent(s2, eFork, 0);
        }

        // 1) G = cm @ cn^T
        tf32gemm_ca<128, 128, 2, 4, true, false, true>
            <<<dim3(4, 4, HB), 256, SM_128_NT, st>>>(
            cm_h, cn_h, G_h, nullptr, CDIM, CDIM, NSP,
            CF, 0, CF, 0, CC, 0, 1, 1.0f);

        // 2) T = G @ cWk^T
        tf32gemm_ca<64, 64, 2, 4, true, false, false>
            <<<dim3(1, 8, HB * NHEADS), 256, SM_64_NT, st>>>(
            G_h, wk_h, T_h, nullptr, CDIM, DH, CDIM,
            CC, 0, 0, (long long)DH * CDIM, (long long)NHEADS * THD, THD,
            NHEADS, 1.0f);

        // 3-4) dots + softmax (double-buffered)
        dots_sm_db<<<dim3(2, HB * NHEADS), 256, 0, st>>>(Wq, T_h, d_h);

        // 5) U = attn @ Wv  (single-iteration BK=64)
        sgemm<64, 64, 64, 4, 4, false, false, true>
            <<<dim3(8, 1, HB * NHEADS), 256, 0, st>>>(
            d_h, Wkv + (size_t)CDIM * CDIM, U_h, nullptr, DH, CDIM, DH,
            (long long)NHEADS * DH * DH, (long long)DH * DH,
            0, (long long)DH * CDIM,
            CC, (long long)DH * CDIM,
            NHEADS, 1.0f);

        // 6) M = cWout @ U
        tf32gemm_ca<128, 128, 2, 4, false, false, true>
            <<<dim3(4, 4, HB), 256, SM_128_NN, st>>>(
            wo_h, U_h, M_h, nullptr, CDIM, CDIM, CDIM,
            0, 0, CC, 0, CC, 0, 1, 1.0f);

        // 7) out = M @ cn + bout
        tf32gemm_ca<256, 128, 4, 2, false, true, false>
            <<<dim3(32, 2, HB), 256, SM_256_NN, st>>>(
            M_h, cn_h, out_h, bout, CDIM, NSP, CDIM,
            CC, 0, CF, 0, CF, 0, 1, 1.0f);
    }

    cudaEventRecord(eJoin, s2);
    cudaStreamWaitEvent((cudaStream_t)0, eJoin, 0);
}